// round 1
// baseline (speedup 1.0000x reference)
#include <cuda_runtime.h>

#define B_   32
#define C_   3
#define H_   512
#define W_   512
#define HW_  (H_ * W_)
#define ROWS 16
#define HB_  (H_ / ROWS)          // 32 row-bands per image
#define NBLK (B_ * HB_)           // 1024 blocks
#define TPB  256
#define TROWS (ROWS + 2)          // 18 tile rows (with halo)
#define STR  516                  // smem row stride (W+2 padded to 516)

__device__ float g_partials[NBLK];

__global__ __launch_bounds__(TPB) void edge_partial_kernel(
    const float* __restrict__ sr, const float* __restrict__ hr)
{
    __shared__ float g[TROWS * STR];

    const int tid = threadIdx.x;
    const int b  = blockIdx.x / HB_;
    const int r0 = (blockIdx.x % HB_) * ROWS;

    const float* srb = sr + (size_t)b * C_ * HW_;
    const float* hrb = hr + (size_t)b * C_ * HW_;

    // Zero the left/right padding columns (cols 0 and W+1 = 513)
    if (tid < 2 * TROWS) {
        int tr  = tid >> 1;
        int col = (tid & 1) ? (W_ + 1) : 0;
        g[tr * STR + col] = 0.0f;
    }

    // Load halo'd gray-diff tile: 18 rows x 128 float4-chunks = 2304 tasks, 9 per thread
    #pragma unroll
    for (int it = 0; it < (TROWS * (W_ / 4)) / TPB; ++it) {
        int idx   = tid + it * TPB;
        int tr    = idx >> 7;          // / 128
        int chunk = idx & 127;
        int gr    = r0 + tr - 1;

        float4 d = make_float4(0.f, 0.f, 0.f, 0.f);
        if (gr >= 0 && gr < H_) {
            size_t off = (size_t)gr * W_ + chunk * 4;
            float4 s0 = *(const float4*)(srb + 0 * HW_ + off);
            float4 s1 = *(const float4*)(srb + 1 * HW_ + off);
            float4 s2 = *(const float4*)(srb + 2 * HW_ + off);
            float4 h0 = *(const float4*)(hrb + 0 * HW_ + off);
            float4 h1 = *(const float4*)(hrb + 1 * HW_ + off);
            float4 h2 = *(const float4*)(hrb + 2 * HW_ + off);
            d.x = 0.2989f * (s0.x - h0.x) + 0.587f * (s1.x - h1.x) + 0.114f * (s2.x - h2.x);
            d.y = 0.2989f * (s0.y - h0.y) + 0.587f * (s1.y - h1.y) + 0.114f * (s2.y - h2.y);
            d.z = 0.2989f * (s0.z - h0.z) + 0.587f * (s1.z - h1.z) + 0.114f * (s2.z - h2.z);
            d.w = 0.2989f * (s0.w - h0.w) + 0.587f * (s1.w - h1.w) + 0.114f * (s2.w - h2.w);
        }
        float* dst = g + tr * STR + 1 + chunk * 4;
        dst[0] = d.x; dst[1] = d.y; dst[2] = d.z; dst[3] = d.w;
    }
    __syncthreads();

    // Sobel + abs + accumulate: 16 rows x 512 cols = 8192 pixels, 32 per thread
    float acc = 0.0f;
    #pragma unroll 4
    for (int it = 0; it < (ROWS * W_) / TPB; ++it) {
        int idx = tid + it * TPB;
        int rr  = idx >> 9;            // / 512  -> 0..15
        int c   = idx & 511;
        const float* p = g + rr * STR + c;   // top-left of 3x3 = (rr, c) in tile coords
        float a00 = p[0],           a01 = p[1],           a02 = p[2];
        float a10 = p[STR],                               a12 = p[STR + 2];
        float a20 = p[2 * STR],     a21 = p[2 * STR + 1], a22 = p[2 * STR + 2];
        float gx = (a00 - a02) + 2.0f * (a10 - a12) + (a20 - a22);
        float gy = (a00 - a20) + 2.0f * (a01 - a21) + (a02 - a22);
        acc += fabsf(gx) + fabsf(gy);
    }

    // Block reduce
    #pragma unroll
    for (int off = 16; off > 0; off >>= 1)
        acc += __shfl_xor_sync(0xFFFFFFFFu, acc, off);

    __shared__ float wsum[TPB / 32];
    if ((tid & 31) == 0) wsum[tid >> 5] = acc;
    __syncthreads();
    if (tid == 0) {
        float s = 0.0f;
        #pragma unroll
        for (int w = 0; w < TPB / 32; ++w) s += wsum[w];
        g_partials[blockIdx.x] = s;
    }
}

__global__ __launch_bounds__(TPB) void edge_finalize_kernel(float* __restrict__ out)
{
    __shared__ double s[TPB];
    double a = 0.0;
    for (int i = threadIdx.x; i < NBLK; i += TPB) a += (double)g_partials[i];
    s[threadIdx.x] = a;
    __syncthreads();
    #pragma unroll
    for (int off = TPB / 2; off > 0; off >>= 1) {
        if (threadIdx.x < off) s[threadIdx.x] += s[threadIdx.x + off];
        __syncthreads();
    }
    if (threadIdx.x == 0)
        out[0] = (float)(s[0] / (double)(B_ * (size_t)HW_));
}

extern "C" void kernel_launch(void* const* d_in, const int* in_sizes, int n_in,
                              void* d_out, int out_size)
{
    const float* sr = (const float*)d_in[0];
    const float* hr = (const float*)d_in[1];
    float* out = (float*)d_out;

    edge_partial_kernel<<<NBLK, TPB>>>(sr, hr);
    edge_finalize_kernel<<<1, TPB>>>(out);
}